// round 6
// baseline (speedup 1.0000x reference)
#include <cuda_runtime.h>
#include <math.h>

#define BB 32
#define SS 2048
#define EE 1024
#define RR 512
#define NSTEPS 8

// ---------------- device state (no allocations allowed) ----------------
__device__ float g_meanpart[BB*16*EE];    // per-(b, seq-chunk) partial sums
__device__ float g_mean[BB*EE];           // mean over seq
__device__ float g_cur[BB*RR];
__device__ float g_h[BB*RR];
__device__ float g_c[BB*RR];
__device__ float g_hsum[BB*RR];           // sum_t w_t * h_t
__device__ float g_final[BB*RR];
__device__ float g_rout[BB*EE];
__device__ float g_Wsum[4*RR*RR];         // W_ih + W_hh  [2048][512]
__device__ float g_encpart[32], g_decpart[32];
__device__ float g_sum_gate;
__device__ int   g_maxmean_i, g_maxfin_i;
__device__ int   g_maxh_i[NSTEPS];
__device__ int   g_trig[NSTEPS];

// ---------------- helpers ----------------
__device__ __forceinline__ float warpRedSum(float v){
    #pragma unroll
    for (int o=16;o;o>>=1) v += __shfl_xor_sync(0xffffffffu, v, o);
    return v;
}
__device__ __forceinline__ float warpRedMax(float v){
    #pragma unroll
    for (int o=16;o;o>>=1) v = fmaxf(v, __shfl_xor_sync(0xffffffffu, v, o));
    return v;
}
__device__ __forceinline__ float sigm(float x){ return 1.f/(1.f+expf(-x)); }
// ternary-weight MAC term: (|w|>thr) ? (w>0 ? a : -a) : 0
__device__ __forceinline__ float terx(float a, float w, float thr){
    float s = (w > 0.f) ? a : -a;
    return (fabsf(w) > thr) ? s : 0.f;
}
__device__ __forceinline__ float quantz(float x, float is){
    return fminf(fmaxf(rintf(x/is), -128.f), 127.f);
}

// ---------------- K_init: Wsum + zero state ----------------
__global__ void k_init(const float* __restrict__ Wih, const float* __restrict__ Whh){
    int gid = blockIdx.x*256 + threadIdx.x;          // 1024*256 = 262144 threads
    float4 a = ((const float4*)Wih)[gid];
    float4 b = ((const float4*)Whh)[gid];
    float4 s; s.x=a.x+b.x; s.y=a.y+b.y; s.z=a.z+b.z; s.w=a.w+b.w;
    ((float4*)g_Wsum)[gid] = s;

    float4 z; z.x=z.y=z.z=z.w=0.f;
    if      (gid < 4096)  ((float4*)g_h)[gid] = z;
    else if (gid < 8192)  ((float4*)g_c)[gid-4096] = z;
    else if (gid < 12288) ((float4*)g_hsum)[gid-8192] = z;
    else if (gid == 12288){
        g_maxmean_i = 0; g_maxfin_i = 0;
        #pragma unroll
        for (int s2=0;s2<NSTEPS;s2++){ g_maxh_i[s2]=0; g_trig[s2]=0; }
    }
}

// ---------------- K_mean: deterministic partials over seq ----------------
__global__ void k_mean(const float* __restrict__ x){
    int b = blockIdx.x, sc = blockIdx.y, t = threadIdx.x;
    const float4* xp = (const float4*)x + (size_t)(b*SS + sc*128)*256;
    float sx=0.f, sy=0.f, sz=0.f, sw=0.f;
    #pragma unroll 4
    for (int r=0;r<128;r++){
        float4 v = xp[r*256 + t];
        sx+=v.x; sy+=v.y; sz+=v.z; sw+=v.w;
    }
    float4 p; p.x=sx; p.y=sy; p.z=sz; p.w=sw;
    ((float4*)g_meanpart)[(b*16+sc)*256 + t] = p;
}

// ---------------- K_scales: finalize mean + |W| sums (all deterministic) ----------------
__global__ void k_scales(const float* __restrict__ encW,
                         const float* __restrict__ decW,
                         const float* __restrict__ gateW){
    __shared__ float red[8];
    int blk = blockIdx.x, t = threadIdx.x;
    int wid = t>>5, lane = t&31;
    if (blk < 32){                            // finalize mean for batch blk + max|mean|
        float m = 0.f;
        for (int i=t;i<EE;i+=256){
            float v = 0.f;
            #pragma unroll
            for (int p=0;p<16;p++) v += g_meanpart[(blk*16+p)*EE + i];
            v *= (1.f/2048.f);
            g_mean[blk*EE + i] = v;
            m = fmaxf(m, fabsf(v));
        }
        m = warpRedMax(m);
        if (lane==0) red[wid]=m;
        __syncthreads();
        if (t==0){
            float mm = red[0];
            #pragma unroll
            for (int i=1;i<8;i++) mm = fmaxf(mm, red[i]);
            atomicMax(&g_maxmean_i, __float_as_int(mm));   // int max: order-independent
        }
    } else if (blk < 96){                     // partial sum|enc_W| / sum|dec_W|
        const float4* Wp = (const float4*)((blk<64) ? encW : decW);
        int c = (blk<64) ? (blk-32) : (blk-64);
        int base = c*4096;                    // float4 chunk (131072 f4 total / 32)
        float s = 0.f;
        #pragma unroll 4
        for (int i=t;i<4096;i+=256){
            float4 v = Wp[base+i];
            s += fabsf(v.x)+fabsf(v.y)+fabsf(v.z)+fabsf(v.w);
        }
        s = warpRedSum(s);
        if (lane==0) red[wid]=s;
        __syncthreads();
        if (t==0){
            float ss = 0.f;
            #pragma unroll
            for (int i=0;i<8;i++) ss += red[i];
            ((blk<64)? g_encpart : g_decpart)[c] = ss;
        }
    } else {                                  // blk==96: sum|gate_W| (512 elems)
        float s = fabsf(gateW[t]) + fabsf(gateW[t+256]);
        s = warpRedSum(s);
        if (lane==0) red[wid]=s;
        __syncthreads();
        if (t==0){
            float ss = 0.f;
            #pragma unroll
            for (int i=0;i<8;i++) ss += red[i];
            g_sum_gate = ss;
        }
    }
}

// ---------------- K_enc: cur = bit_linear(mean, enc_W[512,1024], enc_b) ----------------
#define ENC_SMEM (32*1028*4)   // quantized mean [32][1028] floats (pad 257 f4)
__global__ void k_enc(const float* __restrict__ encW, const float* __restrict__ encB){
    extern __shared__ float sm[];
    float is = __int_as_float(g_maxmean_i) * (1.f/127.f);
    int t = threadIdx.x;
    for (int i4=t; i4<8192; i4+=256){         // 32*1024/4
        int row = i4>>8, col4 = i4&255;
        float4 v = ((const float4*)g_mean)[i4];
        float4 q;
        q.x = quantz(v.x,is); q.y = quantz(v.y,is);
        q.z = quantz(v.z,is); q.w = quantz(v.w,is);
        ((float4*)sm)[row*257 + col4] = q;
    }
    __syncthreads();
    float ssum = 0.f;
    #pragma unroll
    for (int i=0;i<32;i++) ssum += g_encpart[i];
    float wscale = ssum * (1.f/524288.f);
    float thr = 0.5f*wscale;
    int wrp = t>>5, lane = t&31;
    int r = blockIdx.x*8 + wrp;               // 64 blocks * 8 warps = 512 rows
    const float4* Wr   = (const float4*)(encW + r*EE);
    const float4* arow = (const float4*)sm + lane*257;
    float a0=0.f, a1=0.f;
    #pragma unroll 4
    for (int k4=0;k4<256;k4++){
        float4 a = arow[k4];
        float4 w = Wr[k4];
        a0 += terx(a.x,w.x,thr) + terx(a.y,w.y,thr);
        a1 += terx(a.z,w.z,thr) + terx(a.w,w.w,thr);
    }
    g_cur[lane*RR + r] = (a0+a1)*(wscale*is) + encB[r];
}

// ---------------- K_lstm: one fused LSTM step (GEMM + gate-trigger + update) ----------------
// 128 blocks x 256 thr. Block covers r in [r0,r0+4) x 4 gates = 16 output cols.
#define LSTM_SMEM ((32*516 + 512 + 64)*4)
__global__ void k_lstm(const float* __restrict__ Wih,
                       const float* __restrict__ bih, const float* __restrict__ bhh,
                       const float* __restrict__ gateW, const float* __restrict__ gateB,
                       int step){
    extern __shared__ float sm[];
    float* As  = sm;               // [32][516] activations (cur or h)
    float* gs  = sm + 32*516;      // 512 floats scratch / gemm results
    float* aux = gs + 512;         // [0]=step weight; int view [1..32]=per-batch flags
    int t = threadIdx.x;
    const float* Ain = (step==0) ? g_cur : g_h;
    const float* Wp  = (step==0) ? Wih   : g_Wsum;   // cur==h for step>0

    for (int i4=t; i4<4096; i4+=256){          // load A: 32*512/4
        int row = i4>>7, col4 = i4&127;
        ((float4*)As)[row*129 + col4] = ((const float4*)Ain)[i4];
    }
    __syncthreads();

    // prologue: evaluate trigger of step-1 (only steps 3..6 matter -> step>=4)
    if (step >= 4){
        float is  = __int_as_float(g_maxh_i[step-1]) * (1.f/127.f);
        float inv = 1.f / is;
        float gws = g_sum_gate * (1.f/512.f);
        float thr = 0.5f*gws;
        int b = t>>3, part = t&7;
        float acc = 0.f;
        #pragma unroll 8
        for (int i=0;i<64;i++){
            int k = part + (i<<3);
            float a = As[b*516 + k];
            float w = gateW[k];
            float q = fminf(fmaxf(rintf(a*inv), -128.f), 127.f);
            acc += terx(q, w, thr);
        }
        gs[t] = acc;
        __syncthreads();
        if (t < 32){
            float d = 0.f;
            #pragma unroll
            for (int p=0;p<8;p++) d += gs[t*8+p];
            float z = d*gws*is + gateB[0];
            ((int*)aux)[1+t] = (z < 0.f) ? 1 : 0;   // sigmoid(z)<0.5 <=> z<0
        }
        __syncthreads();
        if (t==0){
            int all = 1;
            #pragma unroll
            for (int b2=0;b2<32;b2++) all &= ((int*)aux)[1+b2];
            g_trig[step-1] = all;                   // idempotent across blocks
            float w = 1.f;
            for (int s2=3; s2<step; s2++){
                int tv = (s2==step-1) ? all : g_trig[s2];
                if (tv) w = 0.f;
            }
            aux[0] = w;
        }
        __syncthreads();
    } else {
        if (t==0) aux[0] = 1.f;
        __syncthreads();
    }
    float wsv = aux[0];

    // GEMM: col j = r0 + (l>>2) + ((l&3)<<9), l = warp*2 + {0,1}; lane = batch
    int wrp = t>>5, lane = t&31;
    int r0 = blockIdx.x*4;
    int l0 = wrp*2;
    int j0 = r0 + (l0>>2)     + ((l0&3)<<9);
    int j1 = r0 + ((l0+1)>>2) + (((l0+1)&3)<<9);
    const float4* W0 = (const float4*)(Wp + j0*RR);
    const float4* W1 = (const float4*)(Wp + j1*RR);
    const float4* a4 = (const float4*)(As + lane*516);
    float c00=0.f,c01=0.f,c10=0.f,c11=0.f;
    #pragma unroll 4
    for (int k4=0;k4<128;k4+=2){
        float4 a0 = a4[k4], a1 = a4[k4+1];
        float4 w00=W0[k4], w01=W0[k4+1], w10=W1[k4], w11=W1[k4+1];
        c00 += a0.x*w00.x + a0.y*w00.y + a0.z*w00.z + a0.w*w00.w;
        c01 += a1.x*w01.x + a1.y*w01.y + a1.z*w01.z + a1.w*w01.w;
        c10 += a0.x*w10.x + a0.y*w10.y + a0.z*w10.z + a0.w*w10.w;
        c11 += a1.x*w11.x + a1.y*w11.y + a1.z*w11.z + a1.w*w11.w;
    }
    gs[lane*16 + l0]   = c00 + c01;
    gs[lane*16 + l0+1] = c10 + c11;
    __syncthreads();

    // epilogue: activations + state update (4 r-values x 32 batches = 128 threads)
    if (t < 128){
        int b = t&31, rr = t>>5;
        int r = r0 + rr;
        float gi = gs[b*16 + rr*4 + 0] + bih[r]      + bhh[r];
        float gf = gs[b*16 + rr*4 + 1] + bih[r+512]  + bhh[r+512];
        float gg = gs[b*16 + rr*4 + 2] + bih[r+1024] + bhh[r+1024];
        float go = gs[b*16 + rr*4 + 3] + bih[r+1536] + bhh[r+1536];
        int idx = b*RR + r;
        float cn = sigm(gf)*g_c[idx] + sigm(gi)*tanhf(gg);
        float h  = sigm(go)*tanhf(cn);
        g_c[idx] = cn;
        g_h[idx] = h;
        g_hsum[idx] += wsv * h;
        float m = warpRedMax(fabsf(h));
        if ((t&31)==0) atomicMax(&g_maxh_i[step], __float_as_int(m));
    }
}

// ---------------- K_final: final = hsum / sum(w), max|final| ----------------
__global__ void k_final(){
    __shared__ float red[8];
    int t = threadIdx.x, wid = t>>5, lane = t&31;
    float w = 1.f, ws = 0.f;
    #pragma unroll
    for (int s=0;s<NSTEPS;s++){
        ws += w;                               // weight counted before trigger applies
        if (s>=3 && s<=6 && g_trig[s]) w = 0.f;
    }
    float inv = 1.f/ws, m = 0.f;
    for (int i=t;i<BB*RR;i+=256){
        float v = g_hsum[i] * inv;
        g_final[i] = v;
        m = fmaxf(m, fabsf(v));
    }
    m = warpRedMax(m);
    if (lane==0) red[wid]=m;
    __syncthreads();
    if (t==0){
        float mm = red[0];
        #pragma unroll
        for (int i=1;i<8;i++) mm = fmaxf(mm, red[i]);
        g_maxfin_i = __float_as_int(mm);
    }
}

// ---------------- K_dec: rout = bit_linear(final, dec_W[1024,512], dec_b) ----------------
#define DEC_SMEM (32*516*4)
__global__ void k_dec(const float* __restrict__ decW, const float* __restrict__ decB){
    extern __shared__ float sm[];
    float is = __int_as_float(g_maxfin_i) * (1.f/127.f);
    int t = threadIdx.x;
    for (int i4=t; i4<4096; i4+=256){
        int row = i4>>7, col4 = i4&127;
        float4 v = ((const float4*)g_final)[i4];
        float4 q;
        q.x = quantz(v.x,is); q.y = quantz(v.y,is);
        q.z = quantz(v.z,is); q.w = quantz(v.w,is);
        ((float4*)sm)[row*129 + col4] = q;
    }
    __syncthreads();
    float ssum = 0.f;
    #pragma unroll
    for (int i=0;i<32;i++) ssum += g_decpart[i];
    float wscale = ssum * (1.f/524288.f);
    float thr = 0.5f*wscale;
    int wrp = t>>5, lane = t&31;
    int e = blockIdx.x*8 + wrp;               // 128 blocks * 8 warps = 1024 rows
    const float4* We   = (const float4*)(decW + e*RR);
    const float4* arow = (const float4*)sm + lane*129;
    float a0=0.f, a1=0.f;
    #pragma unroll 4
    for (int k4=0;k4<128;k4++){
        float4 a = arow[k4];
        float4 w = We[k4];
        a0 += terx(a.x,w.x,thr) + terx(a.y,w.y,thr);
        a1 += terx(a.z,w.z,thr) + terx(a.w,w.w,thr);
    }
    g_rout[lane*EE + e] = (a0+a1)*(wscale*is) + decB[e];
}

// ---------------- K_add: out = x + rout (broadcast over seq) ----------------
__global__ void k_add(const float* __restrict__ x, float* __restrict__ out){
    size_t i = (size_t)blockIdx.x*256 + threadIdx.x;   // float4 index, 16777216 total
    float4 xv = ((const float4*)x)[i];
    int e4 = (int)(i & 255);
    int b  = (int)(i >> 19);                            // 2048*256 f4 per batch
    float4 r = ((const float4*)g_rout)[(b<<8) + e4];
    float4 o; o.x=xv.x+r.x; o.y=xv.y+r.y; o.z=xv.z+r.z; o.w=xv.w+r.w;
    ((float4*)out)[i] = o;
}

// ---------------- launch ----------------
extern "C" void kernel_launch(void* const* d_in, const int* in_sizes, int n_in,
                              void* d_out, int out_size){
    const float* x    = (const float*)d_in[0];
    const float* encW = (const float*)d_in[1];
    const float* encB = (const float*)d_in[2];
    const float* Wih  = (const float*)d_in[3];
    const float* Whh  = (const float*)d_in[4];
    const float* bih  = (const float*)d_in[5];
    const float* bhh  = (const float*)d_in[6];
    const float* decW = (const float*)d_in[7];
    const float* decB = (const float*)d_in[8];
    const float* gtW  = (const float*)d_in[9];
    const float* gtB  = (const float*)d_in[10];
    float* out = (float*)d_out;

    cudaFuncSetAttribute(k_enc,  cudaFuncAttributeMaxDynamicSharedMemorySize, ENC_SMEM);
    cudaFuncSetAttribute(k_lstm, cudaFuncAttributeMaxDynamicSharedMemorySize, LSTM_SMEM);
    cudaFuncSetAttribute(k_dec,  cudaFuncAttributeMaxDynamicSharedMemorySize, DEC_SMEM);

    k_init  <<<1024, 256>>>(Wih, Whh);
    k_mean  <<<dim3(32,16), 256>>>(x);
    k_scales<<<97, 256>>>(encW, decW, gtW);
    k_enc   <<<64, 256, ENC_SMEM>>>(encW, encB);
    for (int s = 0; s < NSTEPS; s++)
        k_lstm<<<128, 256, LSTM_SMEM>>>(Wih, bih, bhh, gtW, gtB, s);
    k_final <<<1, 256>>>();
    k_dec   <<<128, 256, DEC_SMEM>>>(decW, decB);
    k_add   <<<65536, 256>>>(x, out);
}

// round 7
// speedup vs baseline: 1.3576x; 1.3576x over previous
#include <cuda_runtime.h>
#include <math.h>

#define BB 32
#define SS 2048
#define EE 1024
#define RR 512
#define NSTEPS 8

// ---------------- device state (no allocations allowed) ----------------
__device__ float g_meanpart[BB*16*EE];    // per-(b, seq-chunk) partial sums
__device__ float g_mean[BB*EE];           // mean over seq
__device__ float g_cur[BB*RR];
__device__ float g_h[BB*RR];
__device__ float g_c[BB*RR];
__device__ float g_hsum[BB*RR];           // sum_t w_t * h_t
__device__ float g_final[BB*RR];
__device__ float g_rout[BB*EE];
__device__ float g_Wsum[4*RR*RR];         // W_ih + W_hh  [2048][512]
__device__ int   g_encQ[RR*EE/4];         // ternary enc weights, packed int8x4
__device__ int   g_decQ[EE*RR/4];         // ternary dec weights, packed int8x4
__device__ float g_encpart[32], g_decpart[32];
__device__ float g_sum_gate;
__device__ int   g_maxmean_i, g_maxfin_i;
__device__ int   g_maxh_i[NSTEPS];
__device__ int   g_trig[NSTEPS];

// ---------------- helpers ----------------
__device__ __forceinline__ float warpRedSum(float v){
    #pragma unroll
    for (int o=16;o;o>>=1) v += __shfl_xor_sync(0xffffffffu, v, o);
    return v;
}
__device__ __forceinline__ float warpRedMax(float v){
    #pragma unroll
    for (int o=16;o;o>>=1) v = fmaxf(v, __shfl_xor_sync(0xffffffffu, v, o));
    return v;
}
__device__ __forceinline__ float sigm(float x){ return 1.f/(1.f+expf(-x)); }
__device__ __forceinline__ float terx(float a, float w, float thr){
    float s = (w > 0.f) ? a : -a;
    return (fabsf(w) > thr) ? s : 0.f;
}
__device__ __forceinline__ float quantz(float x, float is){
    return fminf(fmaxf(rintf(x/is), -128.f), 127.f);
}
__device__ __forceinline__ int tern1(float w, float thr){
    int s = (w > 0.f) ? 1 : -1;
    return (fabsf(w) > thr) ? s : 0;
}
__device__ __forceinline__ int pack4(int a, int b, int c, int d){
    return (a & 0xff) | ((b & 0xff) << 8) | ((c & 0xff) << 16) | (d << 24);
}

// ---------------- K_init: Wsum + zero state ----------------
__global__ void k_init(const float* __restrict__ Wih, const float* __restrict__ Whh){
    int gid = blockIdx.x*256 + threadIdx.x;          // 1024*256 = 262144
    float4 a = ((const float4*)Wih)[gid];
    float4 b = ((const float4*)Whh)[gid];
    float4 s; s.x=a.x+b.x; s.y=a.y+b.y; s.z=a.z+b.z; s.w=a.w+b.w;
    ((float4*)g_Wsum)[gid] = s;

    float4 z; z.x=z.y=z.z=z.w=0.f;
    if      (gid < 4096)  ((float4*)g_h)[gid] = z;
    else if (gid < 8192)  ((float4*)g_c)[gid-4096] = z;
    else if (gid < 12288) ((float4*)g_hsum)[gid-8192] = z;
    else if (gid == 12288){
        g_maxmean_i = 0; g_maxfin_i = 0;
        #pragma unroll
        for (int s2=0;s2<NSTEPS;s2++){ g_maxh_i[s2]=0; g_trig[s2]=0; }
    }
}

// ---------------- K_mean: deterministic partials over seq (streaming loads) ----------------
__global__ void k_mean(const float* __restrict__ x){
    int b = blockIdx.x, sc = blockIdx.y, t = threadIdx.x;
    const float4* xp = (const float4*)x + (size_t)(b*SS + sc*128)*256;
    float sx=0.f, sy=0.f, sz=0.f, sw=0.f;
    #pragma unroll 4
    for (int r=0;r<128;r++){
        float4 v = __ldcs(xp + r*256 + t);
        sx+=v.x; sy+=v.y; sz+=v.z; sw+=v.w;
    }
    float4 p; p.x=sx; p.y=sy; p.z=sz; p.w=sw;
    ((float4*)g_meanpart)[(b*16+sc)*256 + t] = p;
}

// ---------------- K_scales: finalize mean + |W| sums (deterministic) ----------------
__global__ void k_scales(const float* __restrict__ encW,
                         const float* __restrict__ decW,
                         const float* __restrict__ gateW){
    __shared__ float red[8];
    int blk = blockIdx.x, t = threadIdx.x;
    int wid = t>>5, lane = t&31;
    if (blk < 32){
        float m = 0.f;
        for (int i=t;i<EE;i+=256){
            float v = 0.f;
            #pragma unroll
            for (int p=0;p<16;p++) v += g_meanpart[(blk*16+p)*EE + i];
            v *= (1.f/2048.f);
            g_mean[blk*EE + i] = v;
            m = fmaxf(m, fabsf(v));
        }
        m = warpRedMax(m);
        if (lane==0) red[wid]=m;
        __syncthreads();
        if (t==0){
            float mm = red[0];
            #pragma unroll
            for (int i=1;i<8;i++) mm = fmaxf(mm, red[i]);
            atomicMax(&g_maxmean_i, __float_as_int(mm));   // int max: order-independent
        }
    } else if (blk < 96){
        const float4* Wp = (const float4*)((blk<64) ? encW : decW);
        int c = (blk<64) ? (blk-32) : (blk-64);
        int base = c*4096;
        float s = 0.f;
        #pragma unroll 4
        for (int i=t;i<4096;i+=256){
            float4 v = Wp[base+i];
            s += fabsf(v.x)+fabsf(v.y)+fabsf(v.z)+fabsf(v.w);
        }
        s = warpRedSum(s);
        if (lane==0) red[wid]=s;
        __syncthreads();
        if (t==0){
            float ss = 0.f;
            #pragma unroll
            for (int i=0;i<8;i++) ss += red[i];
            ((blk<64)? g_encpart : g_decpart)[c] = ss;
        }
    } else {                                  // blk==96: sum|gate_W|
        float s = fabsf(gateW[t]) + fabsf(gateW[t+256]);
        s = warpRedSum(s);
        if (lane==0) red[wid]=s;
        __syncthreads();
        if (t==0){
            float ss = 0.f;
            #pragma unroll
            for (int i=0;i<8;i++) ss += red[i];
            g_sum_gate = ss;
        }
    }
}

// ---------------- K_pack: ternarize enc/dec weights into packed int8 ----------------
__global__ void k_pack(const float* __restrict__ encW, const float* __restrict__ decW){
    int gid = blockIdx.x*256 + threadIdx.x;   // 1024 blocks -> 262144 float4s
    float se=0.f, sd=0.f;
    #pragma unroll
    for (int i=0;i<32;i++){ se += g_encpart[i]; sd += g_decpart[i]; }
    bool isenc = gid < 131072;
    float thr = 0.5f * (isenc ? se : sd) * (1.f/524288.f);
    int idx = isenc ? gid : gid - 131072;
    float4 w = ((const float4*)(isenc ? encW : decW))[idx];
    int q = pack4(tern1(w.x,thr), tern1(w.y,thr), tern1(w.z,thr), tern1(w.w,thr));
    (isenc ? g_encQ : g_decQ)[idx] = q;
}

// ---------------- K_enc: cur = bit_linear(mean, enc_W[512,1024]) via dp4a ----------------
#define ENC_SMEM (32*257*4)   // packed int8 activations [32][257] words
__global__ void __launch_bounds__(256) k_enc(const float* __restrict__ encB){
    extern __shared__ int smq[];
    float is = __int_as_float(g_maxmean_i) * (1.f/127.f);
    int t = threadIdx.x;
    for (int i4=t; i4<8192; i4+=256){         // 32*1024/4 words
        float4 v = ((const float4*)g_mean)[i4];
        int q = pack4((int)quantz(v.x,is), (int)quantz(v.y,is),
                      (int)quantz(v.z,is), (int)quantz(v.w,is));
        smq[(i4>>8)*257 + (i4&255)] = q;
    }
    __syncthreads();
    float ssum = 0.f;
    #pragma unroll
    for (int i=0;i<32;i++) ssum += g_encpart[i];
    float wscale = ssum * (1.f/524288.f);
    int wrp = t>>5, lane = t&31;
    int r = blockIdx.x*8 + wrp;               // 64 blocks * 8 warps = 512 rows
    const int4* Wq = (const int4*)g_encQ + r*64;
    const int*  ar = smq + lane*257;
    int a0=0,a1=0,a2=0,a3=0;
    #pragma unroll 8
    for (int k=0;k<64;k++){
        int4 wv = Wq[k];
        a0 = __dp4a(ar[4*k+0], wv.x, a0);
        a1 = __dp4a(ar[4*k+1], wv.y, a1);
        a2 = __dp4a(ar[4*k+2], wv.z, a2);
        a3 = __dp4a(ar[4*k+3], wv.w, a3);
    }
    int s = (a0+a1)+(a2+a3);
    g_cur[lane*RR + r] = (float)s * (wscale*is) + encB[r];
}

// ---------------- K_lstm: one fused LSTM step (512 threads, 16 warps) ----------------
// 128 blocks. Block covers r in [r0,r0+4) x 4 gates = 16 columns, 1 col/warp.
#define LSTM_SMEM ((32*516 + 512 + 64)*4)
__global__ void __launch_bounds__(512,1) k_lstm(const float* __restrict__ Wih,
                       const float* __restrict__ bih, const float* __restrict__ bhh,
                       const float* __restrict__ gateW, const float* __restrict__ gateB,
                       int step){
    extern __shared__ float sm[];
    float* As  = sm;               // [32][516] activations (cur or h)
    float* gs  = sm + 32*516;      // 512 floats scratch / gemm results
    float* aux = gs + 512;         // [0]=step weight; int view [1..32]=per-batch flags
    int t = threadIdx.x;
    const float* Ain = (step==0) ? g_cur : g_h;
    const float* Wp  = (step==0) ? Wih   : g_Wsum;   // cur==h for step>0

    for (int i4=t; i4<4096; i4+=512){          // load A: 32*512/4
        int row = i4>>7, col4 = i4&127;
        ((float4*)As)[row*129 + col4] = ((const float4*)Ain)[i4];
    }
    __syncthreads();

    // prologue: evaluate trigger of step-1 (steps 3..6 matter -> step>=4)
    if (step >= 4){
        if (t < 256){
            float is  = __int_as_float(g_maxh_i[step-1]) * (1.f/127.f);
            float inv = 1.f / is;
            float gws = g_sum_gate * (1.f/512.f);
            float thr = 0.5f*gws;
            int b = t>>3, part = t&7;
            float acc = 0.f;
            #pragma unroll 8
            for (int i=0;i<64;i++){
                int k = part + (i<<3);
                float a = As[b*516 + k];
                float w = gateW[k];
                float q = fminf(fmaxf(rintf(a*inv), -128.f), 127.f);
                acc += terx(q, w, thr);
            }
            gs[t] = acc;
        }
        __syncthreads();
        if (t < 32){
            float is  = __int_as_float(g_maxh_i[step-1]) * (1.f/127.f);
            float gws = g_sum_gate * (1.f/512.f);
            float d = 0.f;
            #pragma unroll
            for (int p=0;p<8;p++) d += gs[t*8+p];
            float z = d*gws*is + gateB[0];
            ((int*)aux)[1+t] = (z < 0.f) ? 1 : 0;   // sigmoid(z)<0.5 <=> z<0
        }
        __syncthreads();
        if (t==0){
            int all = 1;
            #pragma unroll
            for (int b2=0;b2<32;b2++) all &= ((int*)aux)[1+b2];
            g_trig[step-1] = all;                   // idempotent across blocks
            float w = 1.f;
            for (int s2=3; s2<step; s2++){
                int tv = (s2==step-1) ? all : g_trig[s2];
                if (tv) w = 0.f;
            }
            aux[0] = w;
        }
        __syncthreads();
    } else {
        if (t==0) aux[0] = 1.f;
        __syncthreads();
    }
    float wsv = aux[0];

    // GEMM: warp l handles col j = r0 + (l>>2) + ((l&3)<<9); lane = batch
    int l = t>>5, lane = t&31;
    int r0 = blockIdx.x*4;
    int j = r0 + (l>>2) + ((l&3)<<9);
    const float4* Wr = (const float4*)(Wp + j*RR);
    const float4* a4 = (const float4*)(As + lane*516);
    float c0=0.f,c1=0.f,c2=0.f,c3=0.f;
    #pragma unroll 2
    for (int k4=0;k4<128;k4+=4){
        float4 a0=a4[k4], a1=a4[k4+1], a2=a4[k4+2], a3=a4[k4+3];
        float4 w0=Wr[k4], w1=Wr[k4+1], w2=Wr[k4+2], w3=Wr[k4+3];
        c0 += a0.x*w0.x + a0.y*w0.y + a0.z*w0.z + a0.w*w0.w;
        c1 += a1.x*w1.x + a1.y*w1.y + a1.z*w1.z + a1.w*w1.w;
        c2 += a2.x*w2.x + a2.y*w2.y + a2.z*w2.z + a2.w*w2.w;
        c3 += a3.x*w3.x + a3.y*w3.y + a3.z*w3.z + a3.w*w3.w;
    }
    gs[lane*16 + l] = (c0+c1)+(c2+c3);
    __syncthreads();

    // epilogue: activations + state update (4 r-values x 32 batches)
    if (t < 128){
        int b = t&31, rr = t>>5;
        int r = r0 + rr;
        float gi = gs[b*16 + rr*4 + 0] + bih[r]      + bhh[r];
        float gf = gs[b*16 + rr*4 + 1] + bih[r+512]  + bhh[r+512];
        float gg = gs[b*16 + rr*4 + 2] + bih[r+1024] + bhh[r+1024];
        float go = gs[b*16 + rr*4 + 3] + bih[r+1536] + bhh[r+1536];
        int idx = b*RR + r;
        float cn = sigm(gf)*g_c[idx] + sigm(gi)*tanhf(gg);
        float h  = sigm(go)*tanhf(cn);
        g_c[idx] = cn;
        g_h[idx] = h;
        g_hsum[idx] += wsv * h;
        float m = warpRedMax(fabsf(h));
        if ((t&31)==0) atomicMax(&g_maxh_i[step], __float_as_int(m));
    }
}

// ---------------- K_final: final = hsum / sum(w), max|final| ----------------
__global__ void k_final(){
    __shared__ float red[8];
    int t = threadIdx.x, wid = t>>5, lane = t&31;
    float w = 1.f, ws = 0.f;
    #pragma unroll
    for (int s=0;s<NSTEPS;s++){
        ws += w;                               // weight counted before trigger applies
        if (s>=3 && s<=6 && g_trig[s]) w = 0.f;
    }
    float inv = 1.f/ws, m = 0.f;
    for (int i=t;i<BB*RR;i+=256){
        float v = g_hsum[i] * inv;
        g_final[i] = v;
        m = fmaxf(m, fabsf(v));
    }
    m = warpRedMax(m);
    if (lane==0) red[wid]=m;
    __syncthreads();
    if (t==0){
        float mm = red[0];
        #pragma unroll
        for (int i=1;i<8;i++) mm = fmaxf(mm, red[i]);
        g_maxfin_i = __float_as_int(mm);
    }
}

// ---------------- K_dec: rout = bit_linear(final, dec_W[1024,512]) via dp4a ----------------
#define DEC_SMEM (32*129*4)
__global__ void __launch_bounds__(256) k_dec(const float* __restrict__ decB){
    extern __shared__ int smq[];
    float is = __int_as_float(g_maxfin_i) * (1.f/127.f);
    int t = threadIdx.x;
    for (int i4=t; i4<4096; i4+=256){         // 32*512/4 words
        float4 v = ((const float4*)g_final)[i4];
        int q = pack4((int)quantz(v.x,is), (int)quantz(v.y,is),
                      (int)quantz(v.z,is), (int)quantz(v.w,is));
        smq[(i4>>7)*129 + (i4&127)] = q;
    }
    __syncthreads();
    float ssum = 0.f;
    #pragma unroll
    for (int i=0;i<32;i++) ssum += g_decpart[i];
    float wscale = ssum * (1.f/524288.f);
    int wrp = t>>5, lane = t&31;
    int e = blockIdx.x*8 + wrp;               // 128 blocks * 8 warps = 1024 rows
    const int4* Wq = (const int4*)g_decQ + e*32;
    const int*  ar = smq + lane*129;
    int a0=0,a1=0,a2=0,a3=0;
    #pragma unroll 8
    for (int k=0;k<32;k++){
        int4 wv = Wq[k];
        a0 = __dp4a(ar[4*k+0], wv.x, a0);
        a1 = __dp4a(ar[4*k+1], wv.y, a1);
        a2 = __dp4a(ar[4*k+2], wv.z, a2);
        a3 = __dp4a(ar[4*k+3], wv.w, a3);
    }
    int s = (a0+a1)+(a2+a3);
    g_rout[lane*EE + e] = (float)s * (wscale*is) + decB[e];
}

// ---------------- K_add: out = x + rout (broadcast over seq, streaming) ----------------
__global__ void k_add(const float* __restrict__ x, float* __restrict__ out){
    size_t i = (size_t)blockIdx.x*256 + threadIdx.x;   // float4 index, 16777216 total
    float4 xv = __ldcs((const float4*)x + i);
    int e4 = (int)(i & 255);
    int b  = (int)(i >> 19);                            // 2048*256 f4 per batch
    float4 r = ((const float4*)g_rout)[(b<<8) + e4];
    float4 o; o.x=xv.x+r.x; o.y=xv.y+r.y; o.z=xv.z+r.z; o.w=xv.w+r.w;
    __stcs((float4*)out + i, o);
}

// ---------------- launch ----------------
extern "C" void kernel_launch(void* const* d_in, const int* in_sizes, int n_in,
                              void* d_out, int out_size){
    const float* x    = (const float*)d_in[0];
    const float* encW = (const float*)d_in[1];
    const float* encB = (const float*)d_in[2];
    const float* Wih  = (const float*)d_in[3];
    const float* Whh  = (const float*)d_in[4];
    const float* bih  = (const float*)d_in[5];
    const float* bhh  = (const float*)d_in[6];
    const float* decW = (const float*)d_in[7];
    const float* decB = (const float*)d_in[8];
    const float* gtW  = (const float*)d_in[9];
    const float* gtB  = (const float*)d_in[10];
    float* out = (float*)d_out;

    cudaFuncSetAttribute(k_enc,  cudaFuncAttributeMaxDynamicSharedMemorySize, ENC_SMEM);
    cudaFuncSetAttribute(k_lstm, cudaFuncAttributeMaxDynamicSharedMemorySize, LSTM_SMEM);
    cudaFuncSetAttribute(k_dec,  cudaFuncAttributeMaxDynamicSharedMemorySize, DEC_SMEM);

    k_init  <<<1024, 256>>>(Wih, Whh);
    k_mean  <<<dim3(32,16), 256>>>(x);
    k_scales<<<97, 256>>>(encW, decW, gtW);
    k_pack  <<<1024, 256>>>(encW, decW);
    k_enc   <<<64, 256, ENC_SMEM>>>(encB);
    for (int s = 0; s < NSTEPS; s++)
        k_lstm<<<128, 512, LSTM_SMEM>>>(Wih, bih, bhh, gtW, gtB, s);
    k_final <<<1, 256>>>();
    k_dec   <<<128, 256, DEC_SMEM>>>(decB);
    k_add   <<<65536, 256>>>(x, out);
}

// round 8
// speedup vs baseline: 1.5294x; 1.1265x over previous
#include <cuda_runtime.h>
#include <math.h>

#define BB 32
#define SS 2048
#define EE 1024
#define RR 512
#define NSTEPS 8
#define MIDG 128
#define MIDT 512

// ---------------- device state (no allocations allowed) ----------------
__device__ float g_meanpart[BB*16*EE];    // per-(b, seq-chunk) partial sums
__device__ float g_mean[BB*EE];
__device__ float g_cur[BB*RR];
__device__ float g_h[BB*RR];
__device__ float g_c[BB*RR];
__device__ float g_hsum[BB*RR];
__device__ float g_final[BB*RR];
__device__ float g_rout[BB*EE];
__device__ float g_Wsum[4*RR*RR];         // W_ih + W_hh  [2048][512]
__device__ int   g_encQ[RR*EE/4];         // ternary enc weights, packed int8x4
__device__ int   g_decQ[EE*RR/4];         // ternary dec weights, packed int8x4
__device__ float g_encpart[32], g_decpart[32];
__device__ float g_sum_gate;
__device__ int   g_maxmean_i, g_maxfin_i;
__device__ int   g_maxh_i[NSTEPS];
__device__ int   g_trig[NSTEPS];
// grid barrier state (monotonic generation -> replay-safe)
__device__ int            g_bcnt = 0;
__device__ volatile unsigned g_bgen = 0;

// ---------------- helpers ----------------
__device__ __forceinline__ float warpRedSum(float v){
    #pragma unroll
    for (int o=16;o;o>>=1) v += __shfl_xor_sync(0xffffffffu, v, o);
    return v;
}
__device__ __forceinline__ float warpRedMax(float v){
    #pragma unroll
    for (int o=16;o;o>>=1) v = fmaxf(v, __shfl_xor_sync(0xffffffffu, v, o));
    return v;
}
__device__ __forceinline__ float sigm(float x){ return 1.f/(1.f+expf(-x)); }
__device__ __forceinline__ float terx(float a, float w, float thr){
    float s = (w > 0.f) ? a : -a;
    return (fabsf(w) > thr) ? s : 0.f;
}
__device__ __forceinline__ float quantz(float x, float is){
    return fminf(fmaxf(rintf(x/is), -128.f), 127.f);
}
__device__ __forceinline__ int tern1(float w, float thr){
    int s = (w > 0.f) ? 1 : -1;
    return (fabsf(w) > thr) ? s : 0;
}
__device__ __forceinline__ int pack4(int a, int b, int c, int d){
    return (a & 0xff) | ((b & 0xff) << 8) | ((c & 0xff) << 16) | (d << 24);
}
// sense-reversing grid barrier; all MIDG blocks resident (MIDG <= #SMs)
__device__ __forceinline__ void gridbar(){
    __syncthreads();
    if (threadIdx.x == 0){
        __threadfence();
        unsigned gen = g_bgen;
        if (atomicAdd(&g_bcnt, 1) == MIDG-1){
            atomicExch(&g_bcnt, 0);
            __threadfence();
            g_bgen = gen + 1;
        } else {
            while (g_bgen == gen) __nanosleep(64);
        }
        __threadfence();
    }
    __syncthreads();
}

// ---------------- K_init: Wsum + zero state (4 f4 per thread) ----------------
__global__ void k_init(const float* __restrict__ Wih, const float* __restrict__ Whh){
    int gid = blockIdx.x*256 + threadIdx.x;          // 256 blocks -> 65536
    #pragma unroll
    for (int k=0;k<4;k++){
        int idx = gid + k*65536;
        float4 a = ((const float4*)Wih)[idx];
        float4 b = ((const float4*)Whh)[idx];
        float4 s; s.x=a.x+b.x; s.y=a.y+b.y; s.z=a.z+b.z; s.w=a.w+b.w;
        ((float4*)g_Wsum)[idx] = s;
    }
    float4 z; z.x=z.y=z.z=z.w=0.f;
    if      (gid < 4096)  ((float4*)g_h)[gid] = z;
    else if (gid < 8192)  ((float4*)g_c)[gid-4096] = z;
    else if (gid < 12288) ((float4*)g_hsum)[gid-8192] = z;
    else if (gid == 12288){
        g_maxmean_i = 0; g_maxfin_i = 0;
        #pragma unroll
        for (int s2=0;s2<NSTEPS;s2++){ g_maxh_i[s2]=0; g_trig[s2]=0; }
    }
}

// ---------------- K_mean: deterministic partials over seq (streaming) ----------------
__global__ void k_mean(const float* __restrict__ x){
    int b = blockIdx.x, sc = blockIdx.y, t = threadIdx.x;
    const float4* xp = (const float4*)x + (size_t)(b*SS + sc*128)*256;
    float sx=0.f, sy=0.f, sz=0.f, sw=0.f;
    #pragma unroll 4
    for (int r=0;r<128;r++){
        float4 v = __ldcs(xp + r*256 + t);
        sx+=v.x; sy+=v.y; sz+=v.z; sw+=v.w;
    }
    float4 p; p.x=sx; p.y=sy; p.z=sz; p.w=sw;
    ((float4*)g_meanpart)[(b*16+sc)*256 + t] = p;
}

// ---------------- K_mid: fused scales+pack+enc+8*lstm+final+dec ----------------
// smem: As[32][516] | gs[1024] | aux[64]  (enc/dec overlay int regions on As)
#define MID_SMEM ((32*516 + 1024 + 64)*4)
__global__ void __launch_bounds__(MIDT,1) k_mid(
    const float* __restrict__ encW, const float* __restrict__ encB,
    const float* __restrict__ Wih,  const float* __restrict__ bih,
    const float* __restrict__ bhh,
    const float* __restrict__ decW, const float* __restrict__ decB,
    const float* __restrict__ gateW, const float* __restrict__ gateB)
{
    extern __shared__ float sm[];
    float* As  = sm;                 // 32*516 floats
    float* gs  = sm + 32*516;        // 1024 floats
    float* aux = gs + 1024;          // 64 floats
    int t = threadIdx.x, blk = blockIdx.x;
    int w = t>>5, lane = t&31;

    // ===== phase 1: scales (mean finalize + |W| partial sums) =====
    {
        float* red = aux;            // 16 warp partials
        if (blk < 32){
            float m = 0.f;
            for (int i=t;i<EE;i+=MIDT){
                float v = 0.f;
                #pragma unroll
                for (int p=0;p<16;p++) v += g_meanpart[(blk*16+p)*EE + i];
                v *= (1.f/2048.f);
                g_mean[blk*EE + i] = v;
                m = fmaxf(m, fabsf(v));
            }
            m = warpRedMax(m);
            if (lane==0) red[w]=m;
            __syncthreads();
            if (t==0){
                float mm = red[0];
                #pragma unroll
                for (int i=1;i<16;i++) mm = fmaxf(mm, red[i]);
                atomicMax(&g_maxmean_i, __float_as_int(mm));
            }
        } else if (blk < 96){
            int c = blk - 32;                      // 0..63
            const float4* Wp = (const float4*)((c<32) ? encW : decW);
            int cc = c & 31;
            int base = cc*4096;
            float s = 0.f;
            #pragma unroll
            for (int i=t;i<4096;i+=MIDT){
                float4 v = Wp[base+i];
                s += fabsf(v.x)+fabsf(v.y)+fabsf(v.z)+fabsf(v.w);
            }
            s = warpRedSum(s);
            if (lane==0) red[w]=s;
            __syncthreads();
            if (t==0){
                float ss = 0.f;
                #pragma unroll
                for (int i=0;i<16;i++) ss += red[i];
                ((c<32)? g_encpart : g_decpart)[cc] = ss;
            }
        } else if (blk == 96){
            float s = fabsf(gateW[t]);            // 512 elems, 512 threads
            s = warpRedSum(s);
            if (lane==0) red[w]=s;
            __syncthreads();
            if (t==0){
                float ss = 0.f;
                #pragma unroll
                for (int i=0;i<16;i++) ss += red[i];
                g_sum_gate = ss;
            }
        }
    }
    gridbar();

    // ===== phase 2: pack ternary weights (4 f4 per thread) =====
    {
        float se=0.f, sd=0.f;
        #pragma unroll
        for (int i=0;i<32;i++){ se += g_encpart[i]; sd += g_decpart[i]; }
        float thre = 0.5f*se*(1.f/524288.f);
        float thrd = 0.5f*sd*(1.f/524288.f);
        #pragma unroll
        for (int k=0;k<4;k++){
            int gid = blk*2048 + k*MIDT + t;      // 0..262143
            bool isenc = gid < 131072;
            float thr = isenc ? thre : thrd;
            int idx = isenc ? gid : gid - 131072;
            float4 wv = ((const float4*)(isenc ? encW : decW))[idx];
            int q = pack4(tern1(wv.x,thr), tern1(wv.y,thr), tern1(wv.z,thr), tern1(wv.w,thr));
            (isenc ? g_encQ : g_decQ)[idx] = q;
        }
    }
    gridbar();

    // ===== phase 3: enc  cur = bit_linear(mean) via dp4a =====
    {
        int* smq = (int*)sm;                      // [32][257] words
        float is = __int_as_float(g_maxmean_i) * (1.f/127.f);
        for (int i4=t; i4<8192; i4+=MIDT){
            float4 v = ((const float4*)g_mean)[i4];
            smq[(i4>>8)*257 + (i4&255)] =
                pack4((int)quantz(v.x,is), (int)quantz(v.y,is),
                      (int)quantz(v.z,is), (int)quantz(v.w,is));
        }
        __syncthreads();
        float ssum = 0.f;
        #pragma unroll
        for (int i=0;i<32;i++) ssum += g_encpart[i];
        float wscale = ssum * (1.f/524288.f);
        int r = blk*4 + (w>>2);                   // 4 rows/block, 4 warps/row (K-split)
        int q = w & 3;
        const int4* Wq = (const int4*)(g_encQ + r*256 + q*64);
        const int*  ar = smq + lane*257 + q*64;
        int a0=0,a1=0,a2=0,a3=0;
        #pragma unroll
        for (int k=0;k<16;k++){
            int4 wv = Wq[k];
            a0 = __dp4a(ar[4*k+0], wv.x, a0);
            a1 = __dp4a(ar[4*k+1], wv.y, a1);
            a2 = __dp4a(ar[4*k+2], wv.z, a2);
            a3 = __dp4a(ar[4*k+3], wv.w, a3);
        }
        int* sp = (int*)(sm + 9024);              // 512 ints
        sp[((w>>2)*32+lane)*4 + q] = (a0+a1)+(a2+a3);
        __syncthreads();
        if (t < 128){
            int rr = t>>5, b = t&31;
            int s = sp[(rr*32+b)*4]+sp[(rr*32+b)*4+1]+sp[(rr*32+b)*4+2]+sp[(rr*32+b)*4+3];
            g_cur[b*RR + blk*4+rr] = (float)s*(wscale*is) + encB[blk*4+rr];
        }
    }
    gridbar();

    // ===== phases 4..11: LSTM steps =====
    for (int step=0; step<NSTEPS; step++){
        const float* Ain = (step==0) ? g_cur : g_h;
        const float* Wp  = (step==0) ? Wih   : g_Wsum;

        for (int i4=t; i4<4096; i4+=MIDT){
            ((float4*)As)[(i4>>7)*129 + (i4&127)] = ((const float4*)Ain)[i4];
        }
        __syncthreads();

        // trigger of step-1 (only steps 3..6 matter -> step>=4)
        if (step >= 4){
            if (t < 256){
                float is  = __int_as_float(g_maxh_i[step-1]) * (1.f/127.f);
                float inv = 1.f / is;
                float gws = g_sum_gate * (1.f/512.f);
                float thr = 0.5f*gws;
                int b = t>>3, part = t&7;
                float acc = 0.f;
                #pragma unroll 8
                for (int i=0;i<64;i++){
                    int k = part + (i<<3);
                    float a = As[b*516 + k];
                    float wv = gateW[k];
                    float qv = fminf(fmaxf(rintf(a*inv), -128.f), 127.f);
                    acc += terx(qv, wv, thr);
                }
                gs[t] = acc;
            }
            __syncthreads();
            if (t < 32){
                float is  = __int_as_float(g_maxh_i[step-1]) * (1.f/127.f);
                float gws = g_sum_gate * (1.f/512.f);
                float d = 0.f;
                #pragma unroll
                for (int p=0;p<8;p++) d += gs[t*8+p];
                float z = d*gws*is + gateB[0];
                ((int*)aux)[1+t] = (z < 0.f) ? 1 : 0;  // sigmoid(z)<0.5 <=> z<0
            }
            __syncthreads();
            if (t==0){
                int all = 1;
                #pragma unroll
                for (int b2=0;b2<32;b2++) all &= ((int*)aux)[1+b2];
                g_trig[step-1] = all;                  // idempotent across blocks
                float wv = 1.f;
                for (int s2=3; s2<step; s2++){
                    int tv = (s2==step-1) ? all : g_trig[s2];
                    if (tv) wv = 0.f;
                }
                aux[0] = wv;
            }
            __syncthreads();
        } else {
            if (t==0) aux[0] = 1.f;
            __syncthreads();
        }
        float wsv = aux[0];

        // GEMM: warp covers 2 cols, K split across warp pairs
        int cg = w>>1, half = w&1;
        int r0 = blk*4;
        int c0 = cg*2, c1 = c0+1;
        int j0 = r0 + (c0>>2) + ((c0&3)<<9);
        int j1 = r0 + (c1>>2) + ((c1&3)<<9);
        const float4* W0 = (const float4*)(Wp + j0*RR);
        const float4* W1 = (const float4*)(Wp + j1*RR);
        const float4* a4 = (const float4*)(As + lane*516);
        int h0 = half*64;
        float p0=0.f,p1=0.f,q0=0.f,q1=0.f;
        #pragma unroll 4
        for (int k4=h0; k4<h0+64; k4+=2){
            float4 a  = a4[k4],   b4 = a4[k4+1];
            float4 x0 = W0[k4],   x1 = W1[k4];
            float4 y0 = W0[k4+1], y1 = W1[k4+1];
            p0 += a.x*x0.x + a.y*x0.y + a.z*x0.z + a.w*x0.w;
            p1 += a.x*x1.x + a.y*x1.y + a.z*x1.z + a.w*x1.w;
            q0 += b4.x*y0.x + b4.y*y0.y + b4.z*y0.z + b4.w*y0.w;
            q1 += b4.x*y1.x + b4.y*y1.y + b4.z*y1.z + b4.w*y1.w;
        }
        gs[(c0*32+lane)*2+half] = p0+q0;
        gs[(c1*32+lane)*2+half] = p1+q1;
        __syncthreads();

        // epilogue
        if (t < 128){
            int b = t&31, rr = t>>5;
            int r = r0 + rr;
            float gi = gs[((rr*4+0)*32+b)*2] + gs[((rr*4+0)*32+b)*2+1] + bih[r]      + bhh[r];
            float gf = gs[((rr*4+1)*32+b)*2] + gs[((rr*4+1)*32+b)*2+1] + bih[r+512]  + bhh[r+512];
            float gg = gs[((rr*4+2)*32+b)*2] + gs[((rr*4+2)*32+b)*2+1] + bih[r+1024] + bhh[r+1024];
            float go = gs[((rr*4+3)*32+b)*2] + gs[((rr*4+3)*32+b)*2+1] + bih[r+1536] + bhh[r+1536];
            int idx = b*RR + r;
            float cn = sigm(gf)*g_c[idx] + sigm(gi)*tanhf(gg);
            float hh = sigm(go)*tanhf(cn);
            g_c[idx] = cn;
            g_h[idx] = hh;
            g_hsum[idx] += wsv * hh;
            float m = warpRedMax(fabsf(hh));
            if ((t&31)==0) atomicMax(&g_maxh_i[step], __float_as_int(m));
        }
        gridbar();
    }

    // ===== phase 12: final = hsum / sum(w), max|final| =====
    {
        float wgt = 1.f, ws = 0.f;
        #pragma unroll
        for (int s=0;s<NSTEPS;s++){
            ws += wgt;
            if (s>=3 && s<=6 && g_trig[s]) wgt = 0.f;
        }
        float inv = 1.f/ws;
        if (t < 128){
            int b = t&31, rr = t>>5;
            int idx = b*RR + blk*4 + rr;
            float v = g_hsum[idx] * inv;
            g_final[idx] = v;
            float m = warpRedMax(fabsf(v));
            if ((t&31)==0) aux[16+(t>>5)] = m;
        }
        __syncthreads();
        if (t==0){
            float mm = fmaxf(fmaxf(aux[16],aux[17]), fmaxf(aux[18],aux[19]));
            atomicMax(&g_maxfin_i, __float_as_int(mm));
        }
    }
    gridbar();

    // ===== phase 13: dec  rout = bit_linear(final) via dp4a =====
    {
        int* smq = (int*)sm;                      // [32][129] words
        float is = __int_as_float(g_maxfin_i) * (1.f/127.f);
        for (int i4=t; i4<4096; i4+=MIDT){
            float4 v = ((const float4*)g_final)[i4];
            smq[(i4>>7)*129 + (i4&127)] =
                pack4((int)quantz(v.x,is), (int)quantz(v.y,is),
                      (int)quantz(v.z,is), (int)quantz(v.w,is));
        }
        __syncthreads();
        float ssum = 0.f;
        #pragma unroll
        for (int i=0;i<32;i++) ssum += g_decpart[i];
        float wscale = ssum * (1.f/524288.f);
        int r = blk*8 + (w>>1);                   // 8 rows/block, 2 warps/row (K-split)
        int half = w & 1;
        const int4* Wq = (const int4*)(g_decQ + r*128 + half*64);
        const int*  ar = smq + lane*129 + half*64;
        int a0=0,a1=0,a2=0,a3=0;
        #pragma unroll
        for (int k=0;k<16;k++){
            int4 wv = Wq[k];
            a0 = __dp4a(ar[4*k+0], wv.x, a0);
            a1 = __dp4a(ar[4*k+1], wv.y, a1);
            a2 = __dp4a(ar[4*k+2], wv.z, a2);
            a3 = __dp4a(ar[4*k+3], wv.w, a3);
        }
        int* sp = (int*)(sm + 4608);              // 512 ints
        sp[((w>>1)*32+lane)*2 + half] = (a0+a1)+(a2+a3);
        __syncthreads();
        if (t < 256){
            int rr = t>>5, b = t&31;              // rr 0..7
            int s = sp[(rr*32+b)*2] + sp[(rr*32+b)*2+1];
            g_rout[b*EE + blk*8+rr] = (float)s*(wscale*is) + decB[blk*8+rr];
        }
    }
}

// ---------------- K_add: out = x + rout (broadcast over seq, streaming) ----------------
__global__ void k_add(const float* __restrict__ x, float* __restrict__ out){
    size_t i = (size_t)blockIdx.x*256 + threadIdx.x;   // float4 index, 16777216 total
    float4 xv = __ldcs((const float4*)x + i);
    int e4 = (int)(i & 255);
    int b  = (int)(i >> 19);
    float4 r = ((const float4*)g_rout)[(b<<8) + e4];
    float4 o; o.x=xv.x+r.x; o.y=xv.y+r.y; o.z=xv.z+r.z; o.w=xv.w+r.w;
    __stcs((float4*)out + i, o);
}

// ---------------- launch ----------------
extern "C" void kernel_launch(void* const* d_in, const int* in_sizes, int n_in,
                              void* d_out, int out_size){
    const float* x    = (const float*)d_in[0];
    const float* encW = (const float*)d_in[1];
    const float* encB = (const float*)d_in[2];
    const float* Wih  = (const float*)d_in[3];
    const float* Whh  = (const float*)d_in[4];
    const float* bih  = (const float*)d_in[5];
    const float* bhh  = (const float*)d_in[6];
    const float* decW = (const float*)d_in[7];
    const float* decB = (const float*)d_in[8];
    const float* gtW  = (const float*)d_in[9];
    const float* gtB  = (const float*)d_in[10];
    float* out = (float*)d_out;

    cudaFuncSetAttribute(k_mid, cudaFuncAttributeMaxDynamicSharedMemorySize, MID_SMEM);

    k_init <<<256, 256>>>(Wih, Whh);
    k_mean <<<dim3(32,16), 256>>>(x);
    k_mid  <<<MIDG, MIDT, MID_SMEM>>>(encW, encB, Wih, bih, bhh, decW, decB, gtW, gtB);
    k_add  <<<65536, 256>>>(x, out);
}

// round 10
// speedup vs baseline: 1.5746x; 1.0296x over previous
#include <cuda_runtime.h>
#include <math.h>

#define BB 32
#define SS 2048
#define EE 1024
#define RR 512
#define NSTEPS 8
#define MIDG 128
#define MIDT 512

// ---------------- device state (no allocations allowed) ----------------
__device__ float g_mean[BB*EE];
__device__ float g_cur[BB*RR];
__device__ float g_h[BB*RR];
__device__ float g_c[BB*RR];
__device__ float g_hsum[BB*RR];
__device__ float g_final[BB*RR];
__device__ float g_rout[BB*EE];
__device__ float g_Wsum[4*RR*RR];         // W_ih + W_hh  [2048][512]
__device__ int   g_encQ[RR*EE/4];         // ternary enc weights, packed int8x4
__device__ int   g_decQ[EE*RR/4];         // ternary dec weights, packed int8x4
__device__ float g_encpart[32], g_decpart[32];
__device__ float g_sum_gate;
__device__ int   g_maxmean_i, g_maxfin_i;
__device__ int   g_maxh_i[NSTEPS];
__device__ int   g_trig[NSTEPS];
// grid barrier state (monotonic generation -> replay-safe)
__device__ int            g_bcnt = 0;
__device__ volatile unsigned g_bgen = 0;

// ---------------- helpers ----------------
__device__ __forceinline__ float warpRedSum(float v){
    #pragma unroll
    for (int o=16;o;o>>=1) v += __shfl_xor_sync(0xffffffffu, v, o);
    return v;
}
__device__ __forceinline__ float warpRedMax(float v){
    #pragma unroll
    for (int o=16;o;o>>=1) v = fmaxf(v, __shfl_xor_sync(0xffffffffu, v, o));
    return v;
}
__device__ __forceinline__ float sigm(float x){ return 1.f/(1.f+expf(-x)); }
__device__ __forceinline__ float terx(float a, float w, float thr){
    float s = (w > 0.f) ? a : -a;
    return (fabsf(w) > thr) ? s : 0.f;
}
__device__ __forceinline__ float quantz(float x, float is){
    return fminf(fmaxf(rintf(x/is), -128.f), 127.f);
}
__device__ __forceinline__ int tern1(float w, float thr){
    int s = (w > 0.f) ? 1 : -1;
    return (fabsf(w) > thr) ? s : 0;
}
__device__ __forceinline__ int pack4(int a, int b, int c, int d){
    return (a & 0xff) | ((b & 0xff) << 8) | ((c & 0xff) << 16) | (d << 24);
}
// sense-reversing grid barrier; all MIDG blocks resident (MIDG <= #SMs)
__device__ __forceinline__ void gridbar(){
    __syncthreads();
    if (threadIdx.x == 0){
        __threadfence();
        unsigned gen = g_bgen;
        if (atomicAdd(&g_bcnt, 1) == MIDG-1){
            atomicExch(&g_bcnt, 0);
            __threadfence();
            g_bgen = gen + 1;
        } else {
            while (g_bgen == gen) __nanosleep(64);
        }
        __threadfence();
    }
    __syncthreads();
}

// ---------------- K_init: Wsum + |W| sums + gate sum + zero state ----------------
__global__ void k_init(const float* __restrict__ Wih, const float* __restrict__ Whh,
                       const float* __restrict__ encW, const float* __restrict__ decW,
                       const float* __restrict__ gateW){
    __shared__ float red[8];
    int blk = blockIdx.x, t = threadIdx.x;
    int w = t>>5, lane = t&31;
    if (blk < 256){
        int gid = blk*256 + t;
        #pragma unroll
        for (int k=0;k<4;k++){
            int idx = gid + k*65536;
            float4 a = ((const float4*)Wih)[idx];
            float4 b = ((const float4*)Whh)[idx];
            float4 s; s.x=a.x+b.x; s.y=a.y+b.y; s.z=a.z+b.z; s.w=a.w+b.w;
            ((float4*)g_Wsum)[idx] = s;
        }
        float4 z; z.x=z.y=z.z=z.w=0.f;
        if      (gid < 4096)  ((float4*)g_h)[gid] = z;
        else if (gid < 8192)  ((float4*)g_c)[gid-4096] = z;
        else if (gid < 12288) ((float4*)g_hsum)[gid-8192] = z;
        else if (gid == 12288){
            g_maxmean_i = 0; g_maxfin_i = 0;
            #pragma unroll
            for (int s2=0;s2<NSTEPS;s2++){ g_maxh_i[s2]=0; g_trig[s2]=0; }
        }
    } else if (blk < 320){
        int c = blk - 256;                        // 0..63
        const float4* Wp = (const float4*)((c<32) ? encW : decW);
        int cc = c & 31;
        float s = 0.f;
        #pragma unroll 4
        for (int i=t;i<4096;i+=256){
            float4 v = Wp[cc*4096+i];
            s += fabsf(v.x)+fabsf(v.y)+fabsf(v.z)+fabsf(v.w);
        }
        s = warpRedSum(s);
        if (lane==0) red[w]=s;
        __syncthreads();
        if (t==0){
            float ss = 0.f;
            #pragma unroll
            for (int i=0;i<8;i++) ss += red[i];
            ((c<32)? g_encpart : g_decpart)[cc] = ss;
        }
    } else {                                      // blk==320: sum|gate_W|
        float s = fabsf(gateW[t]) + fabsf(gateW[t+256]);
        s = warpRedSum(s);
        if (lane==0) red[w]=s;
        __syncthreads();
        if (t==0){
            float ss = 0.f;
            #pragma unroll
            for (int i=0;i<8;i++) ss += red[i];
            g_sum_gate = ss;
        }
    }
}

// ---------------- K_mid: fused mean+pack+enc+8*lstm+final+dec ----------------
#define MID_SMEM ((32*516 + 1024 + 64)*4)
__global__ void __launch_bounds__(MIDT,1) k_mid(
    const float* __restrict__ x,
    const float* __restrict__ encW, const float* __restrict__ encB,
    const float* __restrict__ Wih,  const float* __restrict__ bih,
    const float* __restrict__ bhh,
    const float* __restrict__ decW, const float* __restrict__ decB,
    const float* __restrict__ gateW, const float* __restrict__ gateB)
{
    extern __shared__ float sm[];
    float* As  = sm;                 // 32*516 floats
    float* gs  = sm + 32*516;        // 1024 floats
    float* aux = gs + 1024;          // 64 floats
    int t = threadIdx.x, blk = blockIdx.x;
    int w = t>>5, lane = t&31;

    // ===== phase 0a: pack ternary weights (4 f4 per thread) =====
    {
        float se=0.f, sd=0.f;
        #pragma unroll
        for (int i=0;i<32;i++){ se += g_encpart[i]; sd += g_decpart[i]; }
        float thre = 0.5f*se*(1.f/524288.f);
        float thrd = 0.5f*sd*(1.f/524288.f);
        #pragma unroll
        for (int k=0;k<4;k++){
            int gid = blk*2048 + k*MIDT + t;      // 0..262143
            bool isenc = gid < 131072;
            float thr = isenc ? thre : thrd;
            int idx = isenc ? gid : gid - 131072;
            float4 wv = ((const float4*)(isenc ? encW : decW))[idx];
            (isenc ? g_encQ : g_decQ)[idx] =
                pack4(tern1(wv.x,thr), tern1(wv.y,thr), tern1(wv.z,thr), tern1(wv.w,thr));
        }
    }

    // ===== phase 0b: mean over seq for (batch, 256-col chunk) — no reduction =====
    {
        int b = blk>>2, ec = blk&3;
        const float4* xp = (const float4*)x + (size_t)b*SS*256 + ec*64;
        int row0 = t>>6, col = t&63;              // 8 row groups x 64 f4 cols
        float sx=0.f, sy=0.f, sz=0.f, sw=0.f;
        #pragma unroll 8
        for (int r=row0; r<SS; r+=8){
            float4 v = __ldcs(xp + (size_t)r*256 + col);
            sx+=v.x; sy+=v.y; sz+=v.z; sw+=v.w;
        }
        float4 acc; acc.x=sx; acc.y=sy; acc.z=sz; acc.w=sw;
        ((float4*)sm)[row0*64 + col] = acc;       // [8][256] floats
        __syncthreads();
        if (t < 256){
            float s = 0.f;
            #pragma unroll
            for (int p=0;p<8;p++) s += sm[p*256 + t];
            s *= (1.f/2048.f);
            g_mean[b*EE + ec*256 + t] = s;
            float m = warpRedMax(fabsf(s));
            if ((t&31)==0) atomicMax(&g_maxmean_i, __float_as_int(m));
        }
    }
    gridbar();

    // ===== phase 1: enc  cur = bit_linear(mean) via dp4a =====
    {
        int* smq = (int*)sm;                      // [32][257] words
        float is = __int_as_float(g_maxmean_i) * (1.f/127.f);
        for (int i4=t; i4<8192; i4+=MIDT){
            float4 v = ((const float4*)g_mean)[i4];
            smq[(i4>>8)*257 + (i4&255)] =
                pack4((int)quantz(v.x,is), (int)quantz(v.y,is),
                      (int)quantz(v.z,is), (int)quantz(v.w,is));
        }
        __syncthreads();
        float ssum = 0.f;
        #pragma unroll
        for (int i=0;i<32;i++) ssum += g_encpart[i];
        float wscale = ssum * (1.f/524288.f);
        int r = blk*4 + (w>>2);                   // 4 rows/block, 4 warps/row (K-split)
        int q = w & 3;
        const int4* Wq = (const int4*)(g_encQ + r*256 + q*64);
        const int*  ar = smq + lane*257 + q*64;
        int a0=0,a1=0,a2=0,a3=0;
        #pragma unroll
        for (int k=0;k<16;k++){
            int4 wv = Wq[k];
            a0 = __dp4a(ar[4*k+0], wv.x, a0);
            a1 = __dp4a(ar[4*k+1], wv.y, a1);
            a2 = __dp4a(ar[4*k+2], wv.z, a2);
            a3 = __dp4a(ar[4*k+3], wv.w, a3);
        }
        int* sp = (int*)(sm + 9024);              // 512 ints
        sp[((w>>2)*32+lane)*4 + q] = (a0+a1)+(a2+a3);
        __syncthreads();
        if (t < 128){
            int rr = t>>5, b = t&31;
            int s = sp[(rr*32+b)*4]+sp[(rr*32+b)*4+1]+sp[(rr*32+b)*4+2]+sp[(rr*32+b)*4+3];
            g_cur[b*RR + blk*4+rr] = (float)s*(wscale*is) + encB[blk*4+rr];
        }
    }
    gridbar();

    // ===== phases 2..9: LSTM steps =====
    for (int step=0; step<NSTEPS; step++){
        const float* Ain = (step==0) ? g_cur : g_h;
        const float* Wp  = (step==0) ? Wih   : g_Wsum;

        for (int i4=t; i4<4096; i4+=MIDT){
            ((float4*)As)[(i4>>7)*129 + (i4&127)] = ((const float4*)Ain)[i4];
        }
        __syncthreads();

        // trigger of step-1 (only steps 3..6 matter -> step>=4)
        if (step >= 4){
            if (t < 256){
                float is  = __int_as_float(g_maxh_i[step-1]) * (1.f/127.f);
                float inv = 1.f / is;
                float gws = g_sum_gate * (1.f/512.f);
                float thr = 0.5f*gws;
                int b = t>>3, part = t&7;
                float acc = 0.f;
                #pragma unroll 8
                for (int i=0;i<64;i++){
                    int k = part + (i<<3);
                    float a = As[b*516 + k];
                    float wv = gateW[k];
                    float qv = fminf(fmaxf(rintf(a*inv), -128.f), 127.f);
                    acc += terx(qv, wv, thr);
                }
                gs[t] = acc;
            }
            __syncthreads();
            if (t < 32){
                float is  = __int_as_float(g_maxh_i[step-1]) * (1.f/127.f);
                float gws = g_sum_gate * (1.f/512.f);
                float d = 0.f;
                #pragma unroll
                for (int p=0;p<8;p++) d += gs[t*8+p];
                float z = d*gws*is + gateB[0];
                ((int*)aux)[1+t] = (z < 0.f) ? 1 : 0;  // sigmoid(z)<0.5 <=> z<0
            }
            __syncthreads();
            if (t==0){
                int all = 1;
                #pragma unroll
                for (int b2=0;b2<32;b2++) all &= ((int*)aux)[1+b2];
                g_trig[step-1] = all;                  // idempotent across blocks
                float wv = 1.f;
                for (int s2=3; s2<step; s2++){
                    int tv = (s2==step-1) ? all : g_trig[s2];
                    if (tv) wv = 0.f;
                }
                aux[0] = wv;
            }
            __syncthreads();
        } else {
            if (t==0) aux[0] = 1.f;
            __syncthreads();
        }
        float wsv = aux[0];

        // GEMM: warp covers 2 cols, K split across warp pairs
        int cg = w>>1, half = w&1;
        int r0 = blk*4;
        int c0 = cg*2, c1 = c0+1;
        int j0 = r0 + (c0>>2) + ((c0&3)<<9);
        int j1 = r0 + (c1>>2) + ((c1&3)<<9);
        const float4* W0 = (const float4*)(Wp + j0*RR);
        const float4* W1 = (const float4*)(Wp + j1*RR);
        const float4* a4 = (const float4*)(As + lane*516);
        int h0 = half*64;
        float p0=0.f,p1=0.f,q0=0.f,q1=0.f;
        #pragma unroll 4
        for (int k4=h0; k4<h0+64; k4+=2){
            float4 a  = a4[k4],   b4 = a4[k4+1];
            float4 x0 = W0[k4],   x1 = W1[k4];
            float4 y0 = W0[k4+1], y1 = W1[k4+1];
            p0 += a.x*x0.x + a.y*x0.y + a.z*x0.z + a.w*x0.w;
            p1 += a.x*x1.x + a.y*x1.y + a.z*x1.z + a.w*x1.w;
            q0 += b4.x*y0.x + b4.y*y0.y + b4.z*y0.z + b4.w*y0.w;
            q1 += b4.x*y1.x + b4.y*y1.y + b4.z*y1.z + b4.w*y1.w;
        }
        gs[(c0*32+lane)*2+half] = p0+q0;
        gs[(c1*32+lane)*2+half] = p1+q1;
        __syncthreads();

        // epilogue
        if (t < 128){
            int b = t&31, rr = t>>5;
            int r = r0 + rr;
            float gi = gs[((rr*4+0)*32+b)*2] + gs[((rr*4+0)*32+b)*2+1] + bih[r]      + bhh[r];
            float gf = gs[((rr*4+1)*32+b)*2] + gs[((rr*4+1)*32+b)*2+1] + bih[r+512]  + bhh[r+512];
            float gg = gs[((rr*4+2)*32+b)*2] + gs[((rr*4+2)*32+b)*2+1] + bih[r+1024] + bhh[r+1024];
            float go = gs[((rr*4+3)*32+b)*2] + gs[((rr*4+3)*32+b)*2+1] + bih[r+1536] + bhh[r+1536];
            int idx = b*RR + r;
            float cn = sigm(gf)*g_c[idx] + sigm(gi)*tanhf(gg);
            float hh = sigm(go)*tanhf(cn);
            g_c[idx] = cn;
            g_h[idx] = hh;
            g_hsum[idx] += wsv * hh;
            float m = warpRedMax(fabsf(hh));
            if ((t&31)==0) atomicMax(&g_maxh_i[step], __float_as_int(m));
        }
        gridbar();
    }

    // ===== phase 10: final = hsum / sum(w), max|final| =====
    {
        float wgt = 1.f, ws = 0.f;
        #pragma unroll
        for (int s=0;s<NSTEPS;s++){
            ws += wgt;
            if (s>=3 && s<=6 && g_trig[s]) wgt = 0.f;
        }
        float inv = 1.f/ws;
        if (t < 128){
            int b = t&31, rr = t>>5;
            int idx = b*RR + blk*4 + rr;
            float v = g_hsum[idx] * inv;
            g_final[idx] = v;
            float m = warpRedMax(fabsf(v));
            if ((t&31)==0) aux[16+(t>>5)] = m;
        }
        __syncthreads();
        if (t==0){
            float mm = fmaxf(fmaxf(aux[16],aux[17]), fmaxf(aux[18],aux[19]));
            atomicMax(&g_maxfin_i, __float_as_int(mm));
        }
    }
    gridbar();

    // ===== phase 11: dec  rout = bit_linear(final) via dp4a =====
    {
        int* smq = (int*)sm;                      // [32][129] words
        float is = __int_as_float(g_maxfin_i) * (1.f/127.f);
        for (int i4=t; i4<4096; i4+=MIDT){
            float4 v = ((const float4*)g_final)[i4];
            smq[(i4>>7)*129 + (i4&127)] =
                pack4((int)quantz(v.x,is), (int)quantz(v.y,is),
                      (int)quantz(v.z,is), (int)quantz(v.w,is));
        }
        __syncthreads();
        float ssum = 0.f;
        #pragma unroll
        for (int i=0;i<32;i++) ssum += g_decpart[i];
        float wscale = ssum * (1.f/524288.f);
        int r = blk*8 + (w>>1);                   // 8 rows/block, 2 warps/row (K-split)
        int half = w & 1;
        const int4* Wq = (const int4*)(g_decQ + r*128 + half*64);
        const int*  ar = smq + lane*129 + half*64;
        int a0=0,a1=0,a2=0,a3=0;
        #pragma unroll
        for (int k=0;k<16;k++){
            int4 wv = Wq[k];
            a0 = __dp4a(ar[4*k+0], wv.x, a0);
            a1 = __dp4a(ar[4*k+1], wv.y, a1);
            a2 = __dp4a(ar[4*k+2], wv.z, a2);
            a3 = __dp4a(ar[4*k+3], wv.w, a3);
        }
        int* sp = (int*)(sm + 4608);              // 512 ints
        sp[((w>>1)*32+lane)*2 + half] = (a0+a1)+(a2+a3);
        __syncthreads();
        if (t < 256){
            int rr = t>>5, b = t&31;              // rr 0..7
            int s = sp[(rr*32+b)*2] + sp[(rr*32+b)*2+1];
            g_rout[b*EE + blk*8+rr] = (float)s*(wscale*is) + decB[blk*8+rr];
        }
    }
}

// ---------------- K_add: out = x + rout (broadcast over seq, streaming) ----------------
__global__ void k_add(const float* __restrict__ x, float* __restrict__ out){
    size_t i = (size_t)blockIdx.x*256 + threadIdx.x;   // float4 index, 16777216 total
    float4 xv = __ldcs((const float4*)x + i);
    int e4 = (int)(i & 255);
    int b  = (int)(i >> 19);
    float4 r = ((const float4*)g_rout)[(b<<8) + e4];
    float4 o; o.x=xv.x+r.x; o.y=xv.y+r.y; o.z=xv.z+r.z; o.w=xv.w+r.w;
    __stcs((float4*)out + i, o);
}

// ---------------- launch ----------------
extern "C" void kernel_launch(void* const* d_in, const int* in_sizes, int n_in,
                              void* d_out, int out_size){
    const float* x    = (const float*)d_in[0];
    const float* encW = (const float*)d_in[1];
    const float* encB = (const float*)d_in[2];
    const float* Wih  = (const float*)d_in[3];
    const float* Whh  = (const float*)d_in[4];
    const float* bih  = (const float*)d_in[5];
    const float* bhh  = (const float*)d_in[6];
    const float* decW = (const float*)d_in[7];
    const float* decB = (const float*)d_in[8];
    const float* gtW  = (const float*)d_in[9];
    const float* gtB  = (const float*)d_in[10];
    float* out = (float*)d_out;

    cudaFuncSetAttribute(k_mid, cudaFuncAttributeMaxDynamicSharedMemorySize, MID_SMEM);

    k_init <<<321, 256>>>(Wih, Whh, encW, decW, gtW);
    k_mid  <<<MIDG, MIDT, MID_SMEM>>>(x, encW, encB, Wih, bih, bhh, decW, decB, gtW, gtB);
    k_add  <<<65536, 256>>>(x, out);
}